// round 16
// baseline (speedup 1.0000x reference)
#include <cuda_runtime.h>
#include <math.h>

#define Bc 256
#define Nc 1024
#define Ec 256
#define Hc 8
#define Tc 64
#define SEG 2
#define NSEG 512
#define SUBN 16
#define XPITCH 260
#define XBUF (SUBN * XPITCH)   // 4160 floats per buffer
#define NEG_BIG (-1e30f)
#define CLIPC 10.0f

#define K1 544
#define N1 2176
#define K2 2080
#define N2 288

typedef unsigned long long ull;

// ---------------- f32x2 packed helpers ----------------
__device__ __forceinline__ ull pk2(float lo, float hi) {
    ull r; asm("mov.b64 %0, {%1, %2};" : "=l"(r) : "f"(lo), "f"(hi)); return r;
}
__device__ __forceinline__ void upk2(ull v, float& lo, float& hi) {
    asm("mov.b64 {%0, %1}, %2;" : "=f"(lo), "=f"(hi) : "l"(v));
}
__device__ __forceinline__ void fma2(ull& d, ull a, ull b) {
    asm("fma.rn.f32x2 %0, %1, %2, %0;" : "+l"(d) : "l"(a), "l"(b));
}
__device__ __forceinline__ ull mul2(ull a, ull b) {
    ull r; asm("mul.rn.f32x2 %0, %1, %2;" : "=l"(r) : "l"(a), "l"(b)); return r;
}

// 8-value cross-lane sum reduction with redistribution: 16 shfl.
__device__ __forceinline__ float red8(float s[8], int lane) {
#pragma unroll
    for (int j = 0; j < 8; j++) s[j] += __shfl_xor_sync(0xffffffffu, s[j], 16);
    float k4[4];
    int hi16 = lane & 16;
#pragma unroll
    for (int j = 0; j < 4; j++) k4[j] = hi16 ? s[j + 4] : s[j];
#pragma unroll
    for (int j = 0; j < 4; j++) k4[j] += __shfl_xor_sync(0xffffffffu, k4[j], 8);
    float c0 = (lane & 8) ? k4[2] : k4[0];
    float c1 = (lane & 8) ? k4[3] : k4[1];
    c0 += __shfl_xor_sync(0xffffffffu, c0, 4);
    c1 += __shfl_xor_sync(0xffffffffu, c1, 4);
    float v = (lane & 4) ? c1 : c0;
    v += __shfl_xor_sync(0xffffffffu, v, 2);
    v += __shfl_xor_sync(0xffffffffu, v, 1);
    return v;
}

// ---------------- persistent device state ----------------
__device__ float g_sumx[Bc][Ec];
__device__ float g_cnt[Bc];
__device__ float g_cap[Bc];
__device__ int   g_cur[Bc];
__device__ unsigned char g_visited[Bc][Nc];
__device__ unsigned char g_mask[Bc][Nc];
__device__ float g_part[Bc][SEG][Hc][Ec + 2];
__device__ int   g_syncnt[Bc];
__device__ int   g_pscnt[Bc];
__device__ float g_u[Bc][Nc];

__device__ float g_A1[514][256];
__device__ float g_WkT[256][256];
__device__ float g_Wbig[K1][N1];
__device__ float g_cat[Bc][K1];
__device__ float g_qkflat[Bc][N1];
__device__ float g_T2ext[257][256];
__device__ float g_WpkT[256][256];
__device__ float g_T3ext[257][288];
__device__ float g_G[K2][N2];
__device__ float g_ctxA[Bc][K2];
__device__ float g_qpkpart[8][Bc][N2];

// ======== P1: everything that depends only on inputs ========
__global__ void kP1(const float* __restrict__ x, const float* __restrict__ demand,
                    const float* __restrict__ cap0,
                    const float* __restrict__ Wc, const float* __restrict__ bc,
                    const float* __restrict__ Wqkv, const float* __restrict__ bqkv,
                    const float* __restrict__ Wo, const float* __restrict__ bo,
                    const float* __restrict__ Wpq, const float* __restrict__ bpq,
                    const float* __restrict__ Wpk) {
    int blk = blockIdx.x, t = threadIdx.x;
    if (blk < 256) {
        int b = blk;
        __shared__ int red[8];
        const float* xb = x + (size_t)b * Nc * Ec;
        float s = 0.f;
        for (int n = 0; n < Nc; n++) s += xb[(size_t)n * Ec + t];
        g_sumx[b][t] = s;
        for (int i = t; i < Nc; i += 256) g_visited[b][i] = 0;
        float cap = cap0[b];
        if (t == 0) {
            g_cnt[b] = (float)Nc;
            g_cap[b] = cap;
            g_cur[b] = 0;
            g_syncnt[b] = 0;
            g_pscnt[b] = 0;
        }
        g_cat[b][t] = s / (float)Nc;
        g_cat[b][256 + t] = xb[t];
        if (t == 0) { g_cat[b][512] = cap; g_cat[b][513] = 1.f; }
        if (t < 30) g_cat[b][514 + t] = 0.f;
        int allm = 1;
        for (int n = t; n < Nc; n += 256) {
            int m = (demand[(size_t)b * Nc + n] > cap);
            if (n == 0) m = 1;
            g_mask[b][n] = (unsigned char)m;
            allm &= m;
        }
        allm = __all_sync(0xffffffffu, allm);
        if ((t & 31) == 0) red[t >> 5] = allm;
        __syncthreads();
        if (t == 0) {
            int a = 1;
            for (int w = 0; w < 8; w++) a &= red[w];
            if (a) g_mask[b][0] = 0;
        }
    } else if (blk < 512) {
        int d = blk - 256;
        g_WkT[d][t] = Wqkv[t * 768 + 256 + d];
    } else if (blk < 768) {
        int j2 = blk - 512;
        g_WpkT[j2][t] = Wpk[t * 256 + j2];
    } else if (blk < 1282) {
        int i = blk - 768;
        __shared__ float wrow[256];
        wrow[t] = (i < 513) ? Wc[i * 256 + t] : bc[t];
        __syncthreads();
        float s = (i == 513) ? bqkv[t] : 0.f;
        for (int e = 0; e < 256; e++) s += wrow[e] * Wqkv[e * 768 + t];
        g_A1[i][t] = s;
    } else if (blk < 1539) {
        int i = blk - 1282;
        __shared__ float wrow[256];
        wrow[t] = (i < 256) ? Wo[i * 256 + t] : bo[t];
        __syncthreads();
        float s = (i == 256) ? bpq[t] : 0.f;
        for (int k = 0; k < 256; k++) s += wrow[k] * Wpq[k * 256 + t];
        g_T2ext[i][t] = s;
    } else {
        int idx = (blk - 1539) * 256 + t;
        float* w = &g_Wbig[0][0];
        for (int i = idx; i < K1 * N1; i += 65536) w[i] = 0.f;
        float* g = &g_G[0][0];
        for (int i = idx; i < K2 * N2; i += 65536) g[i] = 0.f;
        for (int i = idx; i < Bc * 31; i += 65536) {
            int b = i / 31, j = i % 31;
            g_ctxA[b][2049 + j] = 0.f;
        }
    }
}

// ======== P2: Wbig (needs A1, WkT) + T3 (needs T2, WpkT) ========
__global__ void kP2(const float* __restrict__ bqkv, const float* __restrict__ bpk) {
    int blk = blockIdx.x, t = threadIdx.x;  // 288 threads
    if (blk < 514) {
        int i = blk;
        __shared__ float a1[256];
        if (t < 256) a1[t] = g_A1[i][t];
        __syncthreads();
        if (t < 256) {
            int e = t;
            const float scale = 0.17677669529663687f;
#pragma unroll
            for (int h = 0; h < 8; h++) {
                float s = 0.f;
#pragma unroll
                for (int dd = 0; dd < 32; dd++) s += a1[h * 32 + dd] * g_WkT[h * 32 + dd][e];
                g_Wbig[i][h * 256 + e] = scale * s;
            }
            if (e < 8) {
                float s = 0.f;
                for (int dd = 0; dd < 32; dd++) s += a1[e * 32 + dd] * bqkv[256 + e * 32 + dd];
                g_Wbig[i][2048 + e] = scale * s;
            }
        }
    } else {
        int j = blk - 514;
        __shared__ float t2[256];
        if (t < 256) t2[t] = g_T2ext[j][t];
        __syncthreads();
        if (t < 256) {
            float s = 0.f;
            for (int k = 0; k < 256; k++) s += t2[k] * g_WpkT[k][t];
            g_T3ext[j][t] = s;
        } else if (t == 256) {
            float s = 0.f;
            for (int k = 0; k < 256; k++) s += t2[k] * bpk[k];
            g_T3ext[j][256] = s;
        }
    }
}

// ======== pG: G fold (needs T3; only used by gemm2) ========
__global__ void pG(const float* __restrict__ Wqkv, const float* __restrict__ bqkv) {
    int he = blockIdx.x, t = threadIdx.x;
    __shared__ float sw[256];
    if (he < 2048) {
        int h = he >> 8, e = he & 255;
        if (t < 32) sw[t] = Wqkv[e * 768 + 512 + h * 32 + t];
        __syncthreads();
        if (t < 257) {
            float s = 0.f;
            int jb = h * 32;
#pragma unroll
            for (int jl = 0; jl < 32; jl++) s += sw[jl] * g_T3ext[jb + jl][t];
            g_G[he][t] = s;
        }
    } else {
        if (t < 256) sw[t] = bqkv[512 + t];
        __syncthreads();
        if (t < 257) {
            float s = g_T3ext[256][t];
            for (int j = 0; j < 256; j++) s += sw[j] * g_T3ext[j][t];
            g_G[2048][t] = s;
        }
    }
}

// ======== GEMM1: qkflat = cat @ Wbig, 32x64 tiles, 272 blocks ========
__global__ void __launch_bounds__(256) k_gemm1() {
    int n0 = blockIdx.x * 64, m0 = blockIdx.y * 32;
    int t = threadIdx.x, tx = t & 31, ty = t >> 5;
    __shared__ __align__(16) float As[32][36];
    __shared__ __align__(16) float Bs[32][64];
    ull acc2[4] = {0ull, 0ull, 0ull, 0ull};
    int srow = t >> 3, sc = t & 7;
    for (int k0 = 0; k0 < K1; k0 += 32) {
        *(float4*)&As[srow][sc * 4] = *(const float4*)&g_cat[m0 + srow][k0 + sc * 4];
        *(float4*)&Bs[srow][sc * 8]     = *(const float4*)&g_Wbig[k0 + srow][n0 + sc * 8];
        *(float4*)&Bs[srow][sc * 8 + 4] = *(const float4*)&g_Wbig[k0 + srow][n0 + sc * 8 + 4];
        __syncthreads();
#pragma unroll
        for (int kk = 0; kk < 32; kk++) {
            ull bv = *(const ull*)&Bs[kk][tx * 2];
#pragma unroll
            for (int i = 0; i < 4; i++) {
                float a = As[ty * 4 + i][kk];
                fma2(acc2[i], pk2(a, a), bv);
            }
        }
        __syncthreads();
    }
#pragma unroll
    for (int i = 0; i < 4; i++) {
        float lo, hi;
        upk2(acc2[i], lo, hi);
        *(float2*)&g_qkflat[m0 + ty * 4 + i][n0 + tx * 2] = make_float2(lo, hi);
    }
}

// ======== K2: flash attention, SEG=2, two 4-warp pipelines, 2-deep ========
// Acc uses dual packing: acc2[d][hp] accumulates heads (2hp, 2hp+1) for local
// dim d, so p-multipliers load pre-packed from smem (no per-head broadcasts).
__global__ void __launch_bounds__(256, 2)
k_attn(const float* __restrict__ x) {
    extern __shared__ __align__(16) float dyn[];
    int seg = blockIdx.x, b = blockIdx.y;
    int t = threadIdx.x, lane = t & 31, w = t >> 5;
    int g = w >> 2, wg = w & 3, tg = t & 127;

    float* xgrp = dyn + g * 2 * XBUF;
    float* ssg  = dyn + 4 * XBUF + g * 192;           // [16][12]
    float* alg  = dyn + 4 * XBUF + 384 + g * 8;       // [8] alphas
    __shared__ int s_last;

    ull qkr2[8][4];
#pragma unroll
    for (int h = 0; h < 8; h++) {
        ulonglong2 q0 = *(const ulonglong2*)&g_qkflat[b][h * 256 + lane * 8];
        ulonglong2 q1 = *(const ulonglong2*)&g_qkflat[b][h * 256 + lane * 8 + 4];
        qkr2[h][0] = q0.x; qkr2[h][1] = q0.y;
        qkr2[h][2] = q1.x; qkr2[h][3] = q1.y;
    }
    int hsm = 2 * wg + (lane >> 4);                   // softmax head (half-warp)
    float sbh = g_qkflat[b][2048 + hsm];

    ull acc2[2][4];
#pragma unroll
    for (int d = 0; d < 2; d++)
#pragma unroll
        for (int hp = 0; hp < 4; hp++) acc2[d][hp] = 0ull;
    float mstate = NEG_BIG, lstate = 0.f;

    int n0 = seg * NSEG + g * SUBN;                   // group chunk base
    unsigned sbase = (unsigned)__cvta_generic_to_shared(xgrp);
    int srow = tg >> 3, scb = tg & 7;

    {   // prologue: stage chunk 0 into buffer 0
        const float4* src = (const float4*)(x + ((size_t)b * Nc + n0) * Ec);
#pragma unroll
        for (int i = 0; i < 8; i++) {
            int c4 = scb + i * 8;
            unsigned d = sbase + (unsigned)(srow * (XPITCH * 4) + c4 * 16);
            asm volatile("cp.async.cg.shared.global [%0], [%1], 16;"
                         :: "r"(d), "l"(src + srow * 64 + c4));
        }
        asm volatile("cp.async.commit_group;");
    }

#pragma unroll 2
    for (int c = 0; c < 16; c++) {
        int ni = n0 + c * 32;
        asm volatile("cp.async.wait_group 0;" ::: "memory");
        asm volatile("bar.sync %0, 128;" :: "r"(1 + g) : "memory");
        if (c < 15) {
            const float4* src = (const float4*)(x + ((size_t)b * Nc + ni + 32) * Ec);
            unsigned bufo = sbase + (unsigned)(((c + 1) & 1) * XBUF * 4);
#pragma unroll
            for (int i = 0; i < 8; i++) {
                int c4 = scb + i * 8;
                unsigned d = bufo + (unsigned)(srow * (XPITCH * 4) + c4 * 16);
                asm volatile("cp.async.cg.shared.global [%0], [%1], 16;"
                             :: "r"(d), "l"(src + srow * 64 + c4));
            }
            asm volatile("cp.async.commit_group;");
        }
        const float* xs = xgrp + (c & 1) * XBUF;

        // ---- scores: warp wg rows wg*4..wg*4+3, all heads ----
#pragma unroll
        for (int i = 0; i < 4; i++) {
            int nl = wg * 4 + i;
            ulonglong2 xva = *(const ulonglong2*)&xs[nl * XPITCH + lane * 8];
            ulonglong2 xvb = *(const ulonglong2*)&xs[nl * XPITCH + lane * 8 + 4];
            ull x2[4] = {xva.x, xva.y, xvb.x, xvb.y};
            float s[8];
#pragma unroll
            for (int h = 0; h < 8; h++) {
                ull s2 = 0ull;
#pragma unroll
                for (int j = 0; j < 4; j++) fma2(s2, qkr2[h][j], x2[j]);
                float lo, hi;
                upk2(s2, lo, hi);
                s[h] = lo + hi;
            }
            float v = red8(s, lane);
            if ((lane & 3) == 0) {
                int h = lane >> 2;
                ssg[nl * 12 + h] = g_mask[b][ni + nl] ? NEG_BIG : v;
            }
        }
        asm volatile("bar.sync %0, 128;" :: "r"(1 + g) : "memory");

        // ---- online softmax: half-warp per head ----
        {
            float raw = ssg[(lane & 15) * 12 + hsm];
            float v = (raw < -1e29f) ? NEG_BIG : raw + sbh;
            float mx = v;
#pragma unroll
            for (int off = 8; off; off >>= 1)
                mx = fmaxf(mx, __shfl_xor_sync(0xffffffffu, mx, off));
            float mnew = fmaxf(mstate, mx);
            float alpha = (mstate > 0.5f * NEG_BIG) ? expf(mstate - mnew) : 0.f;
            float p = (v > 0.5f * NEG_BIG) ? expf(v - mnew) : 0.f;
            ssg[(lane & 15) * 12 + hsm] = p;
            float ps = p;
#pragma unroll
            for (int off = 8; off; off >>= 1)
                ps += __shfl_xor_sync(0xffffffffu, ps, off);
            lstate = lstate * alpha + ps;
            mstate = mnew;
            if ((lane & 15) == 0) alg[hsm] = alpha;
        }
        asm volatile("bar.sync %0, 128;" :: "r"(1 + g) : "memory");

        // ---- acc: warp wg owns dims wg*64 + lane*2 + {0,1}, all heads ----
        {
            float4 af0 = *(const float4*)&alg[0];
            float4 af1 = *(const float4*)&alg[4];
            ull a2[4] = {pk2(af0.x, af0.y), pk2(af0.z, af0.w),
                         pk2(af1.x, af1.y), pk2(af1.z, af1.w)};
#pragma unroll
            for (int d = 0; d < 2; d++)
#pragma unroll
                for (int hp = 0; hp < 4; hp++)
                    acc2[d][hp] = mul2(acc2[d][hp], a2[hp]);
#pragma unroll
            for (int r = 0; r < 16; r++) {
                float2 xv = *(const float2*)&xs[r * XPITCH + wg * 64 + lane * 2];
                ull xp0 = pk2(xv.x, xv.x);
                ull xp1 = pk2(xv.y, xv.y);
                ulonglong2 pa = *(const ulonglong2*)&ssg[r * 12];      // heads 0..3
                ulonglong2 pb = *(const ulonglong2*)&ssg[r * 12 + 4];  // heads 4..7
                fma2(acc2[0][0], xp0, pa.x);
                fma2(acc2[0][1], xp0, pa.y);
                fma2(acc2[0][2], xp0, pb.x);
                fma2(acc2[0][3], xp0, pb.y);
                fma2(acc2[1][0], xp1, pa.x);
                fma2(acc2[1][1], xp1, pa.y);
                fma2(acc2[1][2], xp1, pb.x);
                fma2(acc2[1][3], xp1, pb.y);
            }
        }
    }

    // unpack dual-layout accumulators: av[d][h]
    float av[2][8];
#pragma unroll
    for (int d = 0; d < 2; d++)
#pragma unroll
        for (int hp = 0; hp < 4; hp++)
            upk2(acc2[d][hp], av[d][2 * hp], av[d][2 * hp + 1]);
    int d0 = wg * 64 + lane * 2;

    // ---- cross-group merge (reuse xbuf region) ----
    __syncthreads();
    float* macc = dyn;            // [8][256]
    float* mml  = dyn + 2048;     // [8][2]
    float* mf   = dyn + 2064;     // [8][2]
    if (g == 1) {
        if ((lane & 15) == 0) { mml[hsm * 2] = mstate; mml[hsm * 2 + 1] = lstate; }
#pragma unroll
        for (int h = 0; h < 8; h++)
            *(float2*)&macc[h * 256 + d0] = make_float2(av[0][h], av[1][h]);
    }
    __syncthreads();
    if (g == 0 && (lane & 15) == 0) {
        float mB = mml[hsm * 2], lB = mml[hsm * 2 + 1];
        float M = fmaxf(mstate, mB);
        float fA = (mstate > 0.5f * NEG_BIG) ? expf(mstate - M) : 0.f;
        float fB = (mB > 0.5f * NEG_BIG) ? expf(mB - M) : 0.f;
        g_part[b][seg][hsm][0] = M;
        g_part[b][seg][hsm][1] = fA * lstate + fB * lB;
        mf[hsm * 2] = fA; mf[hsm * 2 + 1] = fB;
    }
    __syncthreads();
    if (g == 0) {
#pragma unroll
        for (int h = 0; h < 8; h++) {
            float fA = mf[h * 2], fB = mf[h * 2 + 1];
            float2 bm = *(const float2*)&macc[h * 256 + d0];
            *(float2*)&g_part[b][seg][h][2 + d0] =
                make_float2(fA * av[0][h] + fB * bm.x, fA * av[1][h] + fB * bm.y);
        }
    }

    // ---- last SEG block for this b performs the merge -> ctxA ----
    __threadfence();
    __syncthreads();
    if (t == 0) {
        int old = atomicAdd(&g_syncnt[b], 1);
        s_last = (old == SEG - 1) ? 1 : 0;
        if (s_last) g_syncnt[b] = 0;
    }
    __syncthreads();
    if (s_last) {
        __threadfence();
#pragma unroll
        for (int h = 0; h < 8; h++) {
            float M = fmaxf(g_part[b][0][h][0], g_part[b][1][h][0]);
            float L = 0.f, a = 0.f;
#pragma unroll
            for (int s = 0; s < SEG; s++) {
                float ms = g_part[b][s][h][0];
                float wgt = (ms > 0.5f * NEG_BIG) ? expf(ms - M) : 0.f;
                L += wgt * g_part[b][s][h][1];
                a += wgt * g_part[b][s][h][2 + t];
            }
            g_ctxA[b][h * 256 + t] = a / L;
        }
        if (t == 0) g_ctxA[b][2048] = 1.f;
    }
}

// ======== GEMM2 (split-K): qpkpart = ctxA @ G ========
__global__ void __launch_bounds__(256) k_gemm2() {
    int n0 = blockIdx.x * 96, m0 = blockIdx.y * 32, s = blockIdx.z;
    int c0 = (s * 65) / 8, c1 = ((s + 1) * 65) / 8;
    int t = threadIdx.x, tx = t & 31, ty = t >> 5;
    __shared__ __align__(16) float As[32][33];
    __shared__ __align__(16) float Bs[32][96];
    float acc[4][3] = {};
    for (int c = c0; c < c1; c++) {
        int k0 = c * 32;
#pragma unroll
        for (int l = 0; l < 4; l++) {
            int idx = t + 256 * l;
            As[idx >> 5][idx & 31] = g_ctxA[m0 + (idx >> 5)][k0 + (idx & 31)];
        }
#pragma unroll
        for (int l = 0; l < 3; l++) {
            int idx = t + 256 * l;
            int r = idx / 24, cc = idx % 24;
            *(float4*)&Bs[r][cc * 4] = *(const float4*)&g_G[k0 + r][n0 + cc * 4];
        }
        __syncthreads();
#pragma unroll
        for (int kk = 0; kk < 32; kk++) {
            float a0 = As[ty * 4 + 0][kk], a1 = As[ty * 4 + 1][kk];
            float a2 = As[ty * 4 + 2][kk], a3 = As[ty * 4 + 3][kk];
            float b0 = Bs[kk][tx * 3 + 0], b1 = Bs[kk][tx * 3 + 1], b2 = Bs[kk][tx * 3 + 2];
            acc[0][0] += a0 * b0; acc[0][1] += a0 * b1; acc[0][2] += a0 * b2;
            acc[1][0] += a1 * b0; acc[1][1] += a1 * b1; acc[1][2] += a1 * b2;
            acc[2][0] += a2 * b0; acc[2][1] += a2 * b1; acc[2][2] += a2 * b2;
            acc[3][0] += a3 * b0; acc[3][1] += a3 * b1; acc[3][2] += a3 * b2;
        }
        __syncthreads();
    }
#pragma unroll
    for (int i = 0; i < 4; i++)
#pragma unroll
        for (int j = 0; j < 3; j++)
            g_qpkpart[s][m0 + ty * 4 + i][n0 + tx * 3 + j] = acc[i][j];
}

// ======== pointer logits (4 blocks/b) + last-block select/update ========
__global__ void __launch_bounds__(256) k_pointsel(
    const float* __restrict__ x, const float* __restrict__ demand,
    float* __restrict__ out, int t_step, int write_route) {
    int s = blockIdx.x, b = blockIdx.y;
    int t = threadIdx.x, lane = t & 31, w = t >> 5;
    __shared__ __align__(16) float qs[Ec];
    __shared__ float s_ub;
    __shared__ int slast;
    __shared__ float rv[8];
    __shared__ int ri[8];
    __shared__ float rs[8];
    __shared__ int redm[8];
    __shared__ int s_node;
    __shared__ float s_max, s_sum;

    {   // split-K reduce of qpk (redundant per block, L2-hot)
        float a = 0.f;
#pragma unroll
        for (int k = 0; k < 8; k++) a += g_qpkpart[k][b][t];
        qs[t] = a;
        if (t == 0) {
            float u = 0.f;
#pragma unroll
            for (int k = 0; k < 8; k++) u += g_qpkpart[k][b][256];
            s_ub = u;
        }
    }
    __syncthreads();
    float ub = s_ub;
    ull q2[4];
    {
        ulonglong2 a0 = *(const ulonglong2*)&qs[lane * 8];
        ulonglong2 a1 = *(const ulonglong2*)&qs[lane * 8 + 4];
        q2[0] = a0.x; q2[1] = a0.y;
        q2[2] = a1.x; q2[3] = a1.y;
    }

    // phase A: this block covers rows s*256 .. s*256+255 (8 warps x 32 rows)
    int rbase = s * 256 + w * 32;
#pragma unroll
    for (int bch = 0; bch < 4; bch++) {
        float sr[8];
#pragma unroll
        for (int r = 0; r < 8; r++) {
            int n = rbase + bch * 8 + r;
            const ulonglong2* xr = (const ulonglong2*)(x + ((size_t)b * Nc + n) * Ec);
            ulonglong2 a0 = xr[lane * 2], a1 = xr[lane * 2 + 1];
            ull acc = 0ull;
            fma2(acc, a0.x, q2[0]);
            fma2(acc, a0.y, q2[1]);
            fma2(acc, a1.x, q2[2]);
            fma2(acc, a1.y, q2[3]);
            float lo, hi;
            upk2(acc, lo, hi);
            sr[r] = lo + hi;
        }
        float v = red8(sr, lane);
        if ((lane & 3) == 0) {
            int n = rbase + bch * 8 + (lane >> 2);
            g_u[b][n] = g_mask[b][n] ? NEG_BIG : CLIPC * tanhf(v + ub);
        }
    }

    // last block per b does selection + output + state update
    __threadfence();
    __syncthreads();
    if (t == 0) {
        int old = atomicAdd(&g_pscnt[b], 1);
        slast = (old == 3) ? 1 : 0;
        if (slast) g_pscnt[b] = 0;
    }
    __syncthreads();
    if (!slast) return;
    __threadfence();

    float cap_old = g_cap[b];
    float cnt_old = g_cnt[b];

    float uv[4];
    float bv = -3.4e38f; int bi = 0x7fffffff;
#pragma unroll
    for (int k = 0; k < 4; k++) {
        int n = t + 256 * k;
        uv[k] = g_u[b][n];
        if (uv[k] > bv) { bv = uv[k]; bi = n; }
    }
#pragma unroll
    for (int off = 16; off; off >>= 1) {
        float ov = __shfl_xor_sync(0xffffffffu, bv, off);
        int oi = __shfl_xor_sync(0xffffffffu, bi, off);
        if (ov > bv || (ov == bv && oi < bi)) { bv = ov; bi = oi; }
    }
    if (lane == 0) { rv[w] = bv; ri[w] = bi; }
    __syncthreads();
    if (t == 0) {
        float mv = rv[0]; int mi = ri[0];
#pragma unroll
        for (int k = 1; k < 8; k++)
            if (rv[k] > mv || (rv[k] == mv && ri[k] < mi)) { mv = rv[k]; mi = ri[k]; }
        s_max = mv; s_node = mi;
    }
    __syncthreads();
    float mx = s_max;
    int node = s_node;

    float pk[4];
    float psum = 0.f;
#pragma unroll
    for (int k = 0; k < 4; k++) { pk[k] = expf(uv[k] - mx); psum += pk[k]; }
#pragma unroll
    for (int off = 16; off; off >>= 1) psum += __shfl_xor_sync(0xffffffffu, psum, off);
    if (lane == 0) rs[w] = psum;
    __syncthreads();
    if (t == 0) {
        float ss = 0.f;
#pragma unroll
        for (int k = 0; k < 8; k++) ss += rs[k];
        s_sum = ss;
    }
    __syncthreads();
    float inv = 1.f / s_sum;
    size_t ob = (size_t)t_step * Bc * Nc + (size_t)b * Nc;
#pragma unroll
    for (int k = 0; k < 4; k++) out[ob + t + 256 * k] = pk[k] * inv;

    // ---- state update for next step ----
    float dnode = demand[(size_t)b * Nc + node];
    float cap_new = cap_old - dnode;
    int nz = (node != 0);
    float cnt_new = cnt_old - (nz ? 1.f : 0.f);

    int vo[4];
#pragma unroll
    for (int k = 0; k < 4; k++) vo[k] = g_visited[b][t + 256 * k];
    __syncthreads();
    if (t == 0) {
        if (write_route) out[(size_t)Tc * Bc * Nc + (size_t)t_step * Bc + b] = (float)node;
        g_cap[b] = cap_new;
        g_cur[b] = node;
        g_cnt[b] = cnt_new;
        if (nz) g_visited[b][node] = 1;
    }
    int allm = 1;
#pragma unroll
    for (int k = 0; k < 4; k++) {
        int n = t + 256 * k;
        int vis = vo[k] | ((n == node) ? nz : 0);
        int m = vis | (demand[(size_t)b * Nc + n] > cap_new);
        if (n == 0) m = (node == 0) ? 1 : m;
        g_mask[b][n] = (unsigned char)m;
        allm &= m;
    }
    allm = __all_sync(0xffffffffu, allm);
    if (lane == 0) redm[w] = allm;

    float xn = x[((size_t)b * Nc + node) * Ec + t];
    float sx = g_sumx[b][t] - (nz ? xn : 0.f);
    g_sumx[b][t] = sx;
    g_cat[b][t] = sx / cnt_new;
    g_cat[b][256 + t] = xn;
    if (t == 0) { g_cat[b][512] = cap_new; g_cat[b][513] = 1.f; }
    __syncthreads();
    if (t == 0) {
        int a = 1;
#pragma unroll
        for (int k = 0; k < 8; k++) a &= redm[k];
        if (a) g_mask[b][0] = 0;
    }
}

// ---------------- launch ----------------
extern "C" void kernel_launch(void* const* d_in, const int* in_sizes, int n_in,
                              void* d_out, int out_size) {
    const float* x      = (const float*)d_in[0];
    const float* demand = (const float*)d_in[1];
    const float* cap0   = (const float*)d_in[2];
    const float* Wc     = (const float*)d_in[3];
    const float* bc     = (const float*)d_in[4];
    const float* Wqkv   = (const float*)d_in[5];
    const float* bqkv   = (const float*)d_in[6];
    const float* Wo     = (const float*)d_in[7];
    const float* bo     = (const float*)d_in[8];
    const float* Wpq    = (const float*)d_in[9];
    const float* bpq    = (const float*)d_in[10];
    const float* Wpk    = (const float*)d_in[11];
    const float* bpk    = (const float*)d_in[12];
    float* out = (float*)d_out;
    int write_route = (out_size > Tc * Bc * Nc) ? 1 : 0;

    const int attn_smem = (4 * XBUF + 2 * 192 + 16) * 4;   // ~66.6 KB
    cudaFuncSetAttribute(k_attn, cudaFuncAttributeMaxDynamicSharedMemorySize, attn_smem);

    kP1<<<1795, 256>>>(x, demand, cap0, Wc, bc, Wqkv, bqkv, Wo, bo, Wpq, bpq, Wpk);
    kP2<<<771, 288>>>(bqkv, bpk);

    for (int t = 0; t < Tc; t++) {
        k_gemm1<<<dim3(34, 8), 256>>>();
        k_attn<<<dim3(SEG, Bc), 256, attn_smem>>>(x);
        if (t == 0) pG<<<2049, 288>>>(Wqkv, bqkv);   // only needed before first gemm2
        k_gemm2<<<dim3(3, 8, 8), 256>>>();
        k_pointsel<<<dim3(4, Bc), 256>>>(x, demand, out, t, write_route);
    }
}

// round 17
// speedup vs baseline: 1.0124x; 1.0124x over previous
#include <cuda_runtime.h>
#include <math.h>

#define Bc 256
#define Nc 1024
#define Ec 256
#define Hc 8
#define Tc 64
#define SEG 2
#define NSEG 512
#define SUBN 16
#define XPITCH 260
#define XBUF (SUBN * XPITCH)   // 4160 floats per buffer
#define NEG_BIG (-1e30f)
#define CLIPC 10.0f

#define K1 544
#define N1 2176
#define K2 2080
#define N2 288

typedef unsigned long long ull;

// ---------------- f32x2 packed helpers ----------------
__device__ __forceinline__ ull pk2(float lo, float hi) {
    ull r; asm("mov.b64 %0, {%1, %2};" : "=l"(r) : "f"(lo), "f"(hi)); return r;
}
__device__ __forceinline__ void upk2(ull v, float& lo, float& hi) {
    asm("mov.b64 {%0, %1}, %2;" : "=f"(lo), "=f"(hi) : "l"(v));
}
__device__ __forceinline__ void fma2(ull& d, ull a, ull b) {
    asm("fma.rn.f32x2 %0, %1, %2, %0;" : "+l"(d) : "l"(a), "l"(b));
}
__device__ __forceinline__ ull mul2(ull a, ull b) {
    ull r; asm("mul.rn.f32x2 %0, %1, %2;" : "=l"(r) : "l"(a), "l"(b)); return r;
}

// 8-value cross-lane sum reduction with redistribution: 16 shfl.
__device__ __forceinline__ float red8(float s[8], int lane) {
#pragma unroll
    for (int j = 0; j < 8; j++) s[j] += __shfl_xor_sync(0xffffffffu, s[j], 16);
    float k4[4];
    int hi16 = lane & 16;
#pragma unroll
    for (int j = 0; j < 4; j++) k4[j] = hi16 ? s[j + 4] : s[j];
#pragma unroll
    for (int j = 0; j < 4; j++) k4[j] += __shfl_xor_sync(0xffffffffu, k4[j], 8);
    float c0 = (lane & 8) ? k4[2] : k4[0];
    float c1 = (lane & 8) ? k4[3] : k4[1];
    c0 += __shfl_xor_sync(0xffffffffu, c0, 4);
    c1 += __shfl_xor_sync(0xffffffffu, c1, 4);
    float v = (lane & 4) ? c1 : c0;
    v += __shfl_xor_sync(0xffffffffu, v, 2);
    v += __shfl_xor_sync(0xffffffffu, v, 1);
    return v;
}

// dual red8: two independent reductions interleaved to overlap shfl latency.
// Per-value math identical to red8 (same op sequence per input array).
__device__ __forceinline__ void red8x2(float s[8], float r[8], int lane,
                                       float& vs, float& vr) {
#pragma unroll
    for (int j = 0; j < 8; j++) {
        s[j] += __shfl_xor_sync(0xffffffffu, s[j], 16);
        r[j] += __shfl_xor_sync(0xffffffffu, r[j], 16);
    }
    float ks[4], kr[4];
    int hi16 = lane & 16;
#pragma unroll
    for (int j = 0; j < 4; j++) {
        ks[j] = hi16 ? s[j + 4] : s[j];
        kr[j] = hi16 ? r[j + 4] : r[j];
    }
#pragma unroll
    for (int j = 0; j < 4; j++) {
        ks[j] += __shfl_xor_sync(0xffffffffu, ks[j], 8);
        kr[j] += __shfl_xor_sync(0xffffffffu, kr[j], 8);
    }
    float cs0 = (lane & 8) ? ks[2] : ks[0];
    float cs1 = (lane & 8) ? ks[3] : ks[1];
    float cr0 = (lane & 8) ? kr[2] : kr[0];
    float cr1 = (lane & 8) ? kr[3] : kr[1];
    cs0 += __shfl_xor_sync(0xffffffffu, cs0, 4);
    cr0 += __shfl_xor_sync(0xffffffffu, cr0, 4);
    cs1 += __shfl_xor_sync(0xffffffffu, cs1, 4);
    cr1 += __shfl_xor_sync(0xffffffffu, cr1, 4);
    float v1 = (lane & 4) ? cs1 : cs0;
    float v2 = (lane & 4) ? cr1 : cr0;
    v1 += __shfl_xor_sync(0xffffffffu, v1, 2);
    v2 += __shfl_xor_sync(0xffffffffu, v2, 2);
    v1 += __shfl_xor_sync(0xffffffffu, v1, 1);
    v2 += __shfl_xor_sync(0xffffffffu, v2, 1);
    vs = v1; vr = v2;
}

// ---------------- persistent device state ----------------
__device__ float g_sumx[Bc][Ec];
__device__ float g_cnt[Bc];
__device__ float g_cap[Bc];
__device__ int   g_cur[Bc];
__device__ unsigned char g_visited[Bc][Nc];
__device__ unsigned char g_mask[Bc][Nc];
__device__ float g_part[Bc][SEG][Hc][Ec + 2];
__device__ int   g_syncnt[Bc];
__device__ int   g_pscnt[Bc];
__device__ float g_u[Bc][Nc];

__device__ float g_A1[514][256];
__device__ float g_WkT[256][256];
__device__ float g_Wbig[K1][N1];
__device__ float g_cat[Bc][K1];
__device__ float g_qkflat[Bc][N1];
__device__ float g_T2ext[257][256];
__device__ float g_WpkT[256][256];
__device__ float g_T3ext[257][288];
__device__ float g_G[K2][N2];
__device__ float g_ctxA[Bc][K2];
__device__ float g_qpkpart[8][Bc][N2];

// ======== P1: everything that depends only on inputs ========
__global__ void kP1(const float* __restrict__ x, const float* __restrict__ demand,
                    const float* __restrict__ cap0,
                    const float* __restrict__ Wc, const float* __restrict__ bc,
                    const float* __restrict__ Wqkv, const float* __restrict__ bqkv,
                    const float* __restrict__ Wo, const float* __restrict__ bo,
                    const float* __restrict__ Wpq, const float* __restrict__ bpq,
                    const float* __restrict__ Wpk) {
    int blk = blockIdx.x, t = threadIdx.x;
    if (blk < 256) {
        int b = blk;
        __shared__ int red[8];
        const float* xb = x + (size_t)b * Nc * Ec;
        float s = 0.f;
        for (int n = 0; n < Nc; n++) s += xb[(size_t)n * Ec + t];
        g_sumx[b][t] = s;
        for (int i = t; i < Nc; i += 256) g_visited[b][i] = 0;
        float cap = cap0[b];
        if (t == 0) {
            g_cnt[b] = (float)Nc;
            g_cap[b] = cap;
            g_cur[b] = 0;
            g_syncnt[b] = 0;
            g_pscnt[b] = 0;
        }
        g_cat[b][t] = s / (float)Nc;
        g_cat[b][256 + t] = xb[t];
        if (t == 0) { g_cat[b][512] = cap; g_cat[b][513] = 1.f; }
        if (t < 30) g_cat[b][514 + t] = 0.f;
        int allm = 1;
        for (int n = t; n < Nc; n += 256) {
            int m = (demand[(size_t)b * Nc + n] > cap);
            if (n == 0) m = 1;
            g_mask[b][n] = (unsigned char)m;
            allm &= m;
        }
        allm = __all_sync(0xffffffffu, allm);
        if ((t & 31) == 0) red[t >> 5] = allm;
        __syncthreads();
        if (t == 0) {
            int a = 1;
            for (int w = 0; w < 8; w++) a &= red[w];
            if (a) g_mask[b][0] = 0;
        }
    } else if (blk < 512) {
        int d = blk - 256;
        g_WkT[d][t] = Wqkv[t * 768 + 256 + d];
    } else if (blk < 768) {
        int j2 = blk - 512;
        g_WpkT[j2][t] = Wpk[t * 256 + j2];
    } else if (blk < 1282) {
        int i = blk - 768;
        __shared__ float wrow[256];
        wrow[t] = (i < 513) ? Wc[i * 256 + t] : bc[t];
        __syncthreads();
        float s = (i == 513) ? bqkv[t] : 0.f;
        for (int e = 0; e < 256; e++) s += wrow[e] * Wqkv[e * 768 + t];
        g_A1[i][t] = s;
    } else if (blk < 1539) {
        int i = blk - 1282;
        __shared__ float wrow[256];
        wrow[t] = (i < 256) ? Wo[i * 256 + t] : bo[t];
        __syncthreads();
        float s = (i == 256) ? bpq[t] : 0.f;
        for (int k = 0; k < 256; k++) s += wrow[k] * Wpq[k * 256 + t];
        g_T2ext[i][t] = s;
    } else {
        int idx = (blk - 1539) * 256 + t;
        float* w = &g_Wbig[0][0];
        for (int i = idx; i < K1 * N1; i += 65536) w[i] = 0.f;
        float* g = &g_G[0][0];
        for (int i = idx; i < K2 * N2; i += 65536) g[i] = 0.f;
        for (int i = idx; i < Bc * 31; i += 65536) {
            int b = i / 31, j = i % 31;
            g_ctxA[b][2049 + j] = 0.f;
        }
    }
}

// ======== P2: Wbig (needs A1, WkT) + T3 (needs T2, WpkT) ========
__global__ void kP2(const float* __restrict__ bqkv, const float* __restrict__ bpk) {
    int blk = blockIdx.x, t = threadIdx.x;  // 288 threads
    if (blk < 514) {
        int i = blk;
        __shared__ float a1[256];
        if (t < 256) a1[t] = g_A1[i][t];
        __syncthreads();
        if (t < 256) {
            int e = t;
            const float scale = 0.17677669529663687f;
#pragma unroll
            for (int h = 0; h < 8; h++) {
                float s = 0.f;
#pragma unroll
                for (int dd = 0; dd < 32; dd++) s += a1[h * 32 + dd] * g_WkT[h * 32 + dd][e];
                g_Wbig[i][h * 256 + e] = scale * s;
            }
            if (e < 8) {
                float s = 0.f;
                for (int dd = 0; dd < 32; dd++) s += a1[e * 32 + dd] * bqkv[256 + e * 32 + dd];
                g_Wbig[i][2048 + e] = scale * s;
            }
        }
    } else {
        int j = blk - 514;
        __shared__ float t2[256];
        if (t < 256) t2[t] = g_T2ext[j][t];
        __syncthreads();
        if (t < 256) {
            float s = 0.f;
            for (int k = 0; k < 256; k++) s += t2[k] * g_WpkT[k][t];
            g_T3ext[j][t] = s;
        } else if (t == 256) {
            float s = 0.f;
            for (int k = 0; k < 256; k++) s += t2[k] * bpk[k];
            g_T3ext[j][256] = s;
        }
    }
}

// ======== pG: G fold (needs T3; only used by gemm2) ========
__global__ void pG(const float* __restrict__ Wqkv, const float* __restrict__ bqkv) {
    int he = blockIdx.x, t = threadIdx.x;
    __shared__ float sw[256];
    if (he < 2048) {
        int h = he >> 8, e = he & 255;
        if (t < 32) sw[t] = Wqkv[e * 768 + 512 + h * 32 + t];
        __syncthreads();
        if (t < 257) {
            float s = 0.f;
            int jb = h * 32;
#pragma unroll
            for (int jl = 0; jl < 32; jl++) s += sw[jl] * g_T3ext[jb + jl][t];
            g_G[he][t] = s;
        }
    } else {
        if (t < 256) sw[t] = bqkv[512 + t];
        __syncthreads();
        if (t < 257) {
            float s = g_T3ext[256][t];
            for (int j = 0; j < 256; j++) s += sw[j] * g_T3ext[j][t];
            g_G[2048][t] = s;
        }
    }
}

// ======== GEMM1: qkflat = cat @ Wbig, 32x64 tiles, 264 blocks ========
__global__ void __launch_bounds__(256) k_gemm1() {
    int n0 = blockIdx.x * 64, m0 = blockIdx.y * 32;
    int t = threadIdx.x, tx = t & 31, ty = t >> 5;
    __shared__ __align__(16) float As[32][36];
    __shared__ __align__(16) float Bs[32][64];
    ull acc2[4] = {0ull, 0ull, 0ull, 0ull};
    int srow = t >> 3, sc = t & 7;
    for (int k0 = 0; k0 < K1; k0 += 32) {
        *(float4*)&As[srow][sc * 4] = *(const float4*)&g_cat[m0 + srow][k0 + sc * 4];
        *(float4*)&Bs[srow][sc * 8]     = *(const float4*)&g_Wbig[k0 + srow][n0 + sc * 8];
        *(float4*)&Bs[srow][sc * 8 + 4] = *(const float4*)&g_Wbig[k0 + srow][n0 + sc * 8 + 4];
        __syncthreads();
#pragma unroll
        for (int kk = 0; kk < 32; kk++) {
            ull bv = *(const ull*)&Bs[kk][tx * 2];
#pragma unroll
            for (int i = 0; i < 4; i++) {
                float a = As[ty * 4 + i][kk];
                fma2(acc2[i], pk2(a, a), bv);
            }
        }
        __syncthreads();
    }
#pragma unroll
    for (int i = 0; i < 4; i++) {
        float lo, hi;
        upk2(acc2[i], lo, hi);
        *(float2*)&g_qkflat[m0 + ty * 4 + i][n0 + tx * 2] = make_float2(lo, hi);
    }
}

// ======== K2: flash attention, SEG=2, two 4-warp pipelines, 2-deep ========
__global__ void __launch_bounds__(256, 2)
k_attn(const float* __restrict__ x) {
    extern __shared__ __align__(16) float dyn[];
    int seg = blockIdx.x, b = blockIdx.y;
    int t = threadIdx.x, lane = t & 31, w = t >> 5;
    int g = w >> 2, wg = w & 3, tg = t & 127;

    float* xgrp = dyn + g * 2 * XBUF;
    float* ssg  = dyn + 4 * XBUF + g * 192;           // [16][12]
    float* alg  = dyn + 4 * XBUF + 384 + g * 8;       // [8] alphas
    __shared__ int s_last;

    ull qkr2[8][4];
#pragma unroll
    for (int h = 0; h < 8; h++) {
        float4 q0 = *(const float4*)&g_qkflat[b][h * 256 + lane * 8];
        float4 q1 = *(const float4*)&g_qkflat[b][h * 256 + lane * 8 + 4];
        qkr2[h][0] = pk2(q0.x, q0.y); qkr2[h][1] = pk2(q0.z, q0.w);
        qkr2[h][2] = pk2(q1.x, q1.y); qkr2[h][3] = pk2(q1.z, q1.w);
    }
    int hsm = 2 * wg + (lane >> 4);                   // softmax head (half-warp)
    float sbh = g_qkflat[b][2048 + hsm];

    ull acc2[8];
#pragma unroll
    for (int h = 0; h < 8; h++) acc2[h] = 0ull;
    float mstate = NEG_BIG, lstate = 0.f;

    int n0 = seg * NSEG + g * SUBN;                   // group chunk base
    unsigned sbase = (unsigned)__cvta_generic_to_shared(xgrp);
    int srow = tg >> 3, scb = tg & 7;

    {   // prologue: stage chunk 0 into buffer 0
        const float4* src = (const float4*)(x + ((size_t)b * Nc + n0) * Ec);
#pragma unroll
        for (int i = 0; i < 8; i++) {
            int c4 = scb + i * 8;
            unsigned d = sbase + (unsigned)(srow * (XPITCH * 4) + c4 * 16);
            asm volatile("cp.async.cg.shared.global [%0], [%1], 16;"
                         :: "r"(d), "l"(src + srow * 64 + c4));
        }
        asm volatile("cp.async.commit_group;");
    }

#pragma unroll 2
    for (int c = 0; c < 16; c++) {
        int ni = n0 + c * 32;
        asm volatile("cp.async.wait_group 0;" ::: "memory");
        asm volatile("bar.sync %0, 128;" :: "r"(1 + g) : "memory");
        if (c < 15) {
            const float4* src = (const float4*)(x + ((size_t)b * Nc + ni + 32) * Ec);
            unsigned bufo = sbase + (unsigned)(((c + 1) & 1) * XBUF * 4);
#pragma unroll
            for (int i = 0; i < 8; i++) {
                int c4 = scb + i * 8;
                unsigned d = bufo + (unsigned)(srow * (XPITCH * 4) + c4 * 16);
                asm volatile("cp.async.cg.shared.global [%0], [%1], 16;"
                             :: "r"(d), "l"(src + srow * 64 + c4));
            }
            asm volatile("cp.async.commit_group;");
        }
        const float* xs = xgrp + (c & 1) * XBUF;

        // ---- scores: warp wg rows wg*4..wg*4+3, all heads, 2-row pairs ----
#pragma unroll
        for (int i2 = 0; i2 < 2; i2++) {
            int nl0 = wg * 4 + i2 * 2;
            float sa[8], sb[8];
            {
                float4 xv0 = *(const float4*)&xs[nl0 * XPITCH + lane * 8];
                float4 xv1 = *(const float4*)&xs[nl0 * XPITCH + lane * 8 + 4];
                ull x2[4] = {pk2(xv0.x, xv0.y), pk2(xv0.z, xv0.w),
                             pk2(xv1.x, xv1.y), pk2(xv1.z, xv1.w)};
#pragma unroll
                for (int h = 0; h < 8; h++) {
                    ull s2 = 0ull;
#pragma unroll
                    for (int j = 0; j < 4; j++) fma2(s2, qkr2[h][j], x2[j]);
                    float lo, hi;
                    upk2(s2, lo, hi);
                    sa[h] = lo + hi;
                }
            }
            {
                float4 xv0 = *(const float4*)&xs[(nl0 + 1) * XPITCH + lane * 8];
                float4 xv1 = *(const float4*)&xs[(nl0 + 1) * XPITCH + lane * 8 + 4];
                ull x2[4] = {pk2(xv0.x, xv0.y), pk2(xv0.z, xv0.w),
                             pk2(xv1.x, xv1.y), pk2(xv1.z, xv1.w)};
#pragma unroll
                for (int h = 0; h < 8; h++) {
                    ull s2 = 0ull;
#pragma unroll
                    for (int j = 0; j < 4; j++) fma2(s2, qkr2[h][j], x2[j]);
                    float lo, hi;
                    upk2(s2, lo, hi);
                    sb[h] = lo + hi;
                }
            }
            float va, vb;
            red8x2(sa, sb, lane, va, vb);
            if ((lane & 3) == 0) {
                int h = lane >> 2;
                ssg[nl0 * 12 + h] = g_mask[b][ni + nl0] ? NEG_BIG : va;
                ssg[(nl0 + 1) * 12 + h] = g_mask[b][ni + nl0 + 1] ? NEG_BIG : vb;
            }
        }
        asm volatile("bar.sync %0, 128;" :: "r"(1 + g) : "memory");

        // ---- online softmax: half-warp per head ----
        {
            float raw = ssg[(lane & 15) * 12 + hsm];
            float v = (raw < -1e29f) ? NEG_BIG : raw + sbh;
            float mx = v;
#pragma unroll
            for (int off = 8; off; off >>= 1)
                mx = fmaxf(mx, __shfl_xor_sync(0xffffffffu, mx, off));
            float mnew = fmaxf(mstate, mx);
            float alpha = (mstate > 0.5f * NEG_BIG) ? expf(mstate - mnew) : 0.f;
            float p = (v > 0.5f * NEG_BIG) ? expf(v - mnew) : 0.f;
            ssg[(lane & 15) * 12 + hsm] = p;
            float ps = p;
#pragma unroll
            for (int off = 8; off; off >>= 1)
                ps += __shfl_xor_sync(0xffffffffu, ps, off);
            lstate = lstate * alpha + ps;
            mstate = mnew;
            if ((lane & 15) == 0) alg[hsm] = alpha;
        }
        asm volatile("bar.sync %0, 128;" :: "r"(1 + g) : "memory");

        // ---- acc: warp wg owns dims wg*64.., all heads, x read once ----
        {
#pragma unroll
            for (int h = 0; h < 8; h++) {
                float a = alg[h];
                acc2[h] = mul2(acc2[h], pk2(a, a));
            }
#pragma unroll
            for (int r = 0; r < 16; r++) {
                float2 xv = *(const float2*)&xs[r * XPITCH + wg * 64 + lane * 2];
                ull xp = pk2(xv.x, xv.y);
                float4 pa = *(const float4*)&ssg[r * 12];
                float4 pb = *(const float4*)&ssg[r * 12 + 4];
                fma2(acc2[0], pk2(pa.x, pa.x), xp);
                fma2(acc2[1], pk2(pa.y, pa.y), xp);
                fma2(acc2[2], pk2(pa.z, pa.z), xp);
                fma2(acc2[3], pk2(pa.w, pa.w), xp);
                fma2(acc2[4], pk2(pb.x, pb.x), xp);
                fma2(acc2[5], pk2(pb.y, pb.y), xp);
                fma2(acc2[6], pk2(pb.z, pb.z), xp);
                fma2(acc2[7], pk2(pb.w, pb.w), xp);
            }
        }
    }

    // ---- cross-group merge (reuse xbuf region) ----
    __syncthreads();
    float* macc = dyn;            // [8][256]
    float* mml  = dyn + 2048;     // [8][2]
    float* mf   = dyn + 2064;     // [8][2]
    if (g == 1) {
        if ((lane & 15) == 0) { mml[hsm * 2] = mstate; mml[hsm * 2 + 1] = lstate; }
#pragma unroll
        for (int h = 0; h < 8; h++) {
            float lo, hi;
            upk2(acc2[h], lo, hi);
            *(float2*)&macc[h * 256 + wg * 64 + lane * 2] = make_float2(lo, hi);
        }
    }
    __syncthreads();
    if (g == 0 && (lane & 15) == 0) {
        float mB = mml[hsm * 2], lB = mml[hsm * 2 + 1];
        float M = fmaxf(mstate, mB);
        float fA = (mstate > 0.5f * NEG_BIG) ? expf(mstate - M) : 0.f;
        float fB = (mB > 0.5f * NEG_BIG) ? expf(mB - M) : 0.f;
        g_part[b][seg][hsm][0] = M;
        g_part[b][seg][hsm][1] = fA * lstate + fB * lB;
        mf[hsm * 2] = fA; mf[hsm * 2 + 1] = fB;
    }
    __syncthreads();
    if (g == 0) {
#pragma unroll
        for (int h = 0; h < 8; h++) {
            float lo, hi;
            upk2(acc2[h], lo, hi);
            float fA = mf[h * 2], fB = mf[h * 2 + 1];
            int d0 = wg * 64 + lane * 2;
            float2 bm = *(const float2*)&macc[h * 256 + d0];
            *(float2*)&g_part[b][seg][h][2 + d0] =
                make_float2(fA * lo + fB * bm.x, fA * hi + fB * bm.y);
        }
    }

    // ---- last SEG block for this b performs the merge -> ctxA ----
    __threadfence();
    __syncthreads();
    if (t == 0) {
        int old = atomicAdd(&g_syncnt[b], 1);
        s_last = (old == SEG - 1) ? 1 : 0;
        if (s_last) g_syncnt[b] = 0;
    }
    __syncthreads();
    if (s_last) {
        __threadfence();
#pragma unroll
        for (int h = 0; h < 8; h++) {
            float M = fmaxf(g_part[b][0][h][0], g_part[b][1][h][0]);
            float L = 0.f, a = 0.f;
#pragma unroll
            for (int s = 0; s < SEG; s++) {
                float ms = g_part[b][s][h][0];
                float wgt = (ms > 0.5f * NEG_BIG) ? expf(ms - M) : 0.f;
                L += wgt * g_part[b][s][h][1];
                a += wgt * g_part[b][s][h][2 + t];
            }
            g_ctxA[b][h * 256 + t] = a / L;
        }
        if (t == 0) g_ctxA[b][2048] = 1.f;
    }
}

// ======== GEMM2 (split-K): qpkpart = ctxA @ G ========
__global__ void __launch_bounds__(256) k_gemm2() {
    int n0 = blockIdx.x * 96, m0 = blockIdx.y * 32, s = blockIdx.z;
    int c0 = (s * 65) / 8, c1 = ((s + 1) * 65) / 8;
    int t = threadIdx.x, tx = t & 31, ty = t >> 5;
    __shared__ __align__(16) float As[32][33];
    __shared__ __align__(16) float Bs[32][96];
    float acc[4][3] = {};
    for (int c = c0; c < c1; c++) {
        int k0 = c * 32;
#pragma unroll
        for (int l = 0; l < 4; l++) {
            int idx = t + 256 * l;
            As[idx >> 5][idx & 31] = g_ctxA[m0 + (idx >> 5)][k0 + (idx & 31)];
        }
#pragma unroll
        for (int l = 0; l < 3; l++) {
            int idx = t + 256 * l;
            int r = idx / 24, cc = idx % 24;
            *(float4*)&Bs[r][cc * 4] = *(const float4*)&g_G[k0 + r][n0 + cc * 4];
        }
        __syncthreads();
#pragma unroll
        for (int kk = 0; kk < 32; kk++) {
            float a0 = As[ty * 4 + 0][kk], a1 = As[ty * 4 + 1][kk];
            float a2 = As[ty * 4 + 2][kk], a3 = As[ty * 4 + 3][kk];
            float b0 = Bs[kk][tx * 3 + 0], b1 = Bs[kk][tx * 3 + 1], b2 = Bs[kk][tx * 3 + 2];
            acc[0][0] += a0 * b0; acc[0][1] += a0 * b1; acc[0][2] += a0 * b2;
            acc[1][0] += a1 * b0; acc[1][1] += a1 * b1; acc[1][2] += a1 * b2;
            acc[2][0] += a2 * b0; acc[2][1] += a2 * b1; acc[2][2] += a2 * b2;
            acc[3][0] += a3 * b0; acc[3][1] += a3 * b1; acc[3][2] += a3 * b2;
        }
        __syncthreads();
    }
#pragma unroll
    for (int i = 0; i < 4; i++)
#pragma unroll
        for (int j = 0; j < 3; j++)
            g_qpkpart[s][m0 + ty * 4 + i][n0 + tx * 3 + j] = acc[i][j];
}

// ======== pointer logits (4 blocks/b) + last-block select/update ========
__global__ void __launch_bounds__(256) k_pointsel(
    const float* __restrict__ x, const float* __restrict__ demand,
    float* __restrict__ out, int t_step, int write_route) {
    int s = blockIdx.x, b = blockIdx.y;
    int t = threadIdx.x, lane = t & 31, w = t >> 5;
    __shared__ float qs[Ec];
    __shared__ float s_ub;
    __shared__ int slast;
    __shared__ float rv[8];
    __shared__ int ri[8];
    __shared__ float rs[8];
    __shared__ int redm[8];
    __shared__ int s_node;
    __shared__ float s_max, s_sum;

    {   // split-K reduce of qpk (redundant per block, L2-hot)
        float a = 0.f;
#pragma unroll
        for (int k = 0; k < 8; k++) a += g_qpkpart[k][b][t];
        qs[t] = a;
        if (t == 0) {
            float u = 0.f;
#pragma unroll
            for (int k = 0; k < 8; k++) u += g_qpkpart[k][b][256];
            s_ub = u;
        }
    }
    __syncthreads();
    float ub = s_ub;
    ull q2[4];
    {
        float4 a0 = *(const float4*)&qs[lane * 8];
        float4 a1 = *(const float4*)&qs[lane * 8 + 4];
        q2[0] = pk2(a0.x, a0.y); q2[1] = pk2(a0.z, a0.w);
        q2[2] = pk2(a1.x, a1.y); q2[3] = pk2(a1.z, a1.w);
    }

    // phase A: this block covers rows s*256 .. s*256+255 (8 warps x 32 rows)
    int rbase = s * 256 + w * 32;
#pragma unroll
    for (int bch = 0; bch < 4; bch++) {
        float sr[8];
#pragma unroll
        for (int r = 0; r < 8; r++) {
            int n = rbase + bch * 8 + r;
            const float4* xr = (const float4*)(x + ((size_t)b * Nc + n) * Ec);
            float4 a0 = xr[lane * 2], a1 = xr[lane * 2 + 1];
            ull acc = 0ull;
            fma2(acc, pk2(a0.x, a0.y), q2[0]);
            fma2(acc, pk2(a0.z, a0.w), q2[1]);
            fma2(acc, pk2(a1.x, a1.y), q2[2]);
            fma2(acc, pk2(a1.z, a1.w), q2[3]);
            float lo, hi;
            upk2(acc, lo, hi);
            sr[r] = lo + hi;
        }
        float v = red8(sr, lane);
        if ((lane & 3) == 0) {
            int n = rbase + bch * 8 + (lane >> 2);
            g_u[b][n] = g_mask[b][n] ? NEG_BIG : CLIPC * tanhf(v + ub);
        }
    }

    // last block per b does selection + output + state update
    __threadfence();
    __syncthreads();
    if (t == 0) {
        int old = atomicAdd(&g_pscnt[b], 1);
        slast = (old == 3) ? 1 : 0;
        if (slast) g_pscnt[b] = 0;
    }
    __syncthreads();
    if (!slast) return;
    __threadfence();

    float cap_old = g_cap[b];
    float cnt_old = g_cnt[b];

    float uv[4];
    float bv = -3.4e38f; int bi = 0x7fffffff;
#pragma unroll
    for (int k = 0; k < 4; k++) {
        int n = t + 256 * k;
        uv[k] = g_u[b][n];
        if (uv[k] > bv) { bv = uv[k]; bi = n; }
    }
#pragma unroll
    for (int off = 16; off; off >>= 1) {
        float ov = __shfl_xor_sync(0xffffffffu, bv, off);
        int oi = __shfl_xor_sync(0xffffffffu, bi, off);
        if (ov > bv || (ov == bv && oi < bi)) { bv = ov; bi = oi; }
    }
    if (lane == 0) { rv[w] = bv; ri[w] = bi; }
    __syncthreads();
    if (t == 0) {
        float mv = rv[0]; int mi = ri[0];
#pragma unroll
        for (int k = 1; k < 8; k++)
            if (rv[k] > mv || (rv[k] == mv && ri[k] < mi)) { mv = rv[k]; mi = ri[k]; }
        s_max = mv; s_node = mi;
    }
    __syncthreads();
    float mx = s_max;
    int node = s_node;

    float pk[4];
    float psum = 0.f;
#pragma unroll
    for (int k = 0; k < 4; k++) { pk[k] = expf(uv[k] - mx); psum += pk[k]; }
#pragma unroll
    for (int off = 16; off; off >>= 1) psum += __shfl_xor_sync(0xffffffffu, psum, off);
    if (lane == 0) rs[w] = psum;
    __syncthreads();
    if (t == 0) {
        float ss = 0.f;
#pragma unroll
        for (int k = 0; k < 8; k++) ss += rs[k];
        s_sum = ss;
    }
    __syncthreads();
    float inv = 1.f / s_sum;
    size_t ob = (size_t)t_step * Bc * Nc + (size_t)b * Nc;
#pragma unroll
    for (int k = 0; k < 4; k++) out[ob + t + 256 * k] = pk[k] * inv;

    // ---- state update for next step ----
    float dnode = demand[(size_t)b * Nc + node];
    float cap_new = cap_old - dnode;
    int nz = (node != 0);
    float cnt_new = cnt_old - (nz ? 1.f : 0.f);

    int vo[4];
#pragma unroll
    for (int k = 0; k < 4; k++) vo[k] = g_visited[b][t + 256 * k];
    __syncthreads();
    if (t == 0) {
        if (write_route) out[(size_t)Tc * Bc * Nc + (size_t)t_step * Bc + b] = (float)node;
        g_cap[b] = cap_new;
        g_cur[b] = node;
        g_cnt[b] = cnt_new;
        if (nz) g_visited[b][node] = 1;
    }
    int allm = 1;
#pragma unroll
    for (int k = 0; k < 4; k++) {
        int n = t + 256 * k;
        int vis = vo[k] | ((n == node) ? nz : 0);
        int m = vis | (demand[(size_t)b * Nc + n] > cap_new);
        if (n == 0) m = (node == 0) ? 1 : m;
        g_mask[b][n] = (unsigned char)m;
        allm &= m;
    }
    allm = __all_sync(0xffffffffu, allm);
    if (lane == 0) redm[w] = allm;

    float xn = x[((size_t)b * Nc + node) * Ec + t];
    float sx = g_sumx[b][t] - (nz ? xn : 0.f);
    g_sumx[b][t] = sx;
    g_cat[b][t] = sx / cnt_new;
    g_cat[b][256 + t] = xn;
    if (t == 0) { g_cat[b][512] = cap_new; g_cat[b][513] = 1.f; }
    __syncthreads();
    if (t == 0) {
        int a = 1;
#pragma unroll
        for (int k = 0; k < 8; k++) a &= redm[k];
        if (a) g_mask[b][0] = 0;
    }
}

// ---------------- launch ----------------
extern "C" void kernel_launch(void* const* d_in, const int* in_sizes, int n_in,
                              void* d_out, int out_size) {
    const float* x      = (const float*)d_in[0];
    const float* demand = (const float*)d_in[1];
    const float* cap0   = (const float*)d_in[2];
    const float* Wc     = (const float*)d_in[3];
    const float* bc     = (const float*)d_in[4];
    const float* Wqkv   = (const float*)d_in[5];
    const float* bqkv   = (const float*)d_in[6];
    const float* Wo     = (const float*)d_in[7];
    const float* bo     = (const float*)d_in[8];
    const float* Wpq    = (const float*)d_in[9];
    const float* bpq    = (const float*)d_in[10];
    const float* Wpk    = (const float*)d_in[11];
    const float* bpk    = (const float*)d_in[12];
    float* out = (float*)d_out;
    int write_route = (out_size > Tc * Bc * Nc) ? 1 : 0;

    const int attn_smem = (4 * XBUF + 2 * 192 + 16) * 4;   // ~66.6 KB
    cudaFuncSetAttribute(k_attn, cudaFuncAttributeMaxDynamicSharedMemorySize, attn_smem);

    kP1<<<1795, 256>>>(x, demand, cap0, Wc, bc, Wqkv, bqkv, Wo, bo, Wpq, bpq, Wpk);
    kP2<<<771, 288>>>(bqkv, bpk);

    for (int t = 0; t < Tc; t++) {
        k_gemm1<<<dim3(33, 8), 256>>>();
        k_attn<<<dim3(SEG, Bc), 256, attn_smem>>>(x);
        if (t == 0) pG<<<2049, 288>>>(Wqkv, bqkv);   // only needed before first gemm2
        k_gemm2<<<dim3(3, 8, 8), 256>>>();
        k_pointsel<<<dim3(4, Bc), 256>>>(x, demand, out, t, write_route);
    }
}